// round 10
// baseline (speedup 1.0000x reference)
#include <cuda_runtime.h>
#include <cstdint>

#define HDIM 128
#define TSEQ 512
#define BATCH 128
#define GB 8            // batches per cluster
#define RSTRIDE 132
#define WSTRIDE 132
#define GSTRIDE 9       // gate-buffer row stride (conflict-free scalar access)

typedef unsigned long long u64;

__device__ float g_h2[(size_t)TSEQ * BATCH * HDIM];   // [t][b][h]
__device__ float g_dold[TSEQ * BATCH];
__device__ float g_dh[TSEQ * BATCH];

__device__ __forceinline__ float sigm(float x) {
    return __fdividef(1.f, 1.f + __expf(-x));
}
__device__ __forceinline__ float tanh_fast(float x) {
    x = fminf(fmaxf(x, -15.f), 15.f);
    float e = __expf(2.f * x);
    return __fdividef(e - 1.f, e + 1.f);
}
__device__ __forceinline__ u64 ffma2(u64 a, u64 b, u64 c) {
    u64 d;
    asm("fma.rn.f32x2 %0, %1, %2, %3;" : "=l"(d) : "l"(a), "l"(b), "l"(c));
    return d;
}
__device__ __forceinline__ float sum2(u64 v) {
    float lo, hi;
    asm("mov.b64 {%0, %1}, %2;" : "=f"(lo), "=f"(hi) : "l"(v));
    return lo + hi;
}
__device__ __forceinline__ void st_cluster_f32(float* p, int rank, float v) {
    uint32_t la = (uint32_t)__cvta_generic_to_shared(p);
    uint32_t ra;
    asm volatile("mapa.shared::cluster.u32 %0, %1, %2;" : "=r"(ra) : "r"(la), "r"(rank));
    asm volatile("st.shared::cluster.f32 [%0], %1;" :: "r"(ra), "f"(v) : "memory");
}
__device__ __forceinline__ void mbar_init(uint32_t a, uint32_t cnt) {
    asm volatile("mbarrier.init.shared.b64 [%0], %1;" :: "r"(a), "r"(cnt) : "memory");
}
__device__ __forceinline__ void mbar_arrive_rank(uint32_t local_addr, uint32_t rank) {
    asm volatile(
        "{\n\t.reg .b32 ra;\n\t"
        "mapa.shared::cluster.u32 ra, %0, %1;\n\t"
        "mbarrier.arrive.release.cluster.shared::cluster.b64 _, [ra];\n\t}"
        :: "r"(local_addr), "r"(rank) : "memory");
}
__device__ __forceinline__ void mbar_wait(uint32_t addr, uint32_t parity) {
    asm volatile(
        "{\n\t.reg .pred P;\n"
        "WL_%=:\n\t"
        "mbarrier.try_wait.parity.acquire.cluster.shared::cta.b64 P, [%0], %1, 0x989680;\n\t"
        "@P bra WD_%=;\n\t"
        "bra WL_%=;\n"
        "WD_%=:\n\t}"
        :: "r"(addr), "r"(parity) : "memory");
}
__device__ __forceinline__ void cluster_sync_() {
    asm volatile("barrier.cluster.arrive.aligned;" ::: "memory");
    asm volatile("barrier.cluster.wait.aligned;" ::: "memory");
}

// ---------------------------------------------------------------------------
// Phase 1: 16 clusters x 4 CTAs, 8 batches/cluster, 256 threads/CTA.
// Amortization: the per-step fixed costs (weight SMEM reads, DSMEM handshake,
// barriers) are paid once for EIGHT batches instead of four.
//   mv1: thread = (row j1 = tid&127, batch-quad bh = tid>>7). Full row from
//        SMEM (32 LDS.128, conflict-free: rows 528B apart), activations are
//        warp-uniform broadcasts. 256 FFMA2, 4 chains.
//   mv2: thread = gate row of Wih2 (tid<128) or Whh2 (tid>=128), weights in
//        REGISTERS (64 u64), 8 batches = 8 chains, 512 FFMA2, broadcasts only.
// Gate buffers use row stride 9 floats -> conflict-free scalar ld/st.
// Pipelined (iter i: cell1 step i on tid<128, cell2 step i-1 on tid>=128),
// split mbarriers as R5. __syncthreads() before cells; release-arrives after
// per-half bar.sync cover all RAW/WAR (same invariant chain as R5).
// ---------------------------------------------------------------------------
__global__ void __launch_bounds__(256, 1) __cluster_dims__(4, 1, 1)
lstm_seq_kernel(const float* __restrict__ x,
                const float* __restrict__ Wih1, const float* __restrict__ Whh1,
                const float* __restrict__ bih1, const float* __restrict__ bhh1,
                const float* __restrict__ Wih2, const float* __restrict__ Whh2,
                const float* __restrict__ bih2, const float* __restrict__ bhh2)
{
    extern __shared__ float sW1[];                       // [128][WSTRIDE]

    __shared__ __align__(16) float h1bc[2][GB][HDIM];    // [parity][b][h]
    __shared__ __align__(16) float c1bc[2][GB][HDIM];
    __shared__ __align__(16) float h2bc[2][GB][HDIM];
    __shared__ float xs[GB][TSEQ];                       // 16 KB
    __shared__ float g1buf[128 * GSTRIDE];               // [row*9 + b]
    __shared__ float part2[256 * GSTRIDE];               // [vrow*9 + b]
    __shared__ float bias1s[128], bias2s[128], wih1s[128];
    __shared__ __align__(8) u64 mbar[2];

    const int tid  = threadIdx.x;
    const int rank = blockIdx.x & 3;
    const int bg0  = (blockIdx.x >> 2) * GB;

    const int j1 = tid & 127;          // mv1 row / mv2 row
    const int bh = tid >> 7;           // mv1 batch-quad
    const int m2 = tid >> 7;           // mv2 matrix select
    const int cu  = tid & 31,          cb  = (tid >> 5) & 3;   // cell1 (tid<128)
    const int cu2 = (tid - 128) & 31,  cb2 = ((tid - 128) >> 5) & 3; // cell2
    const int slot1 = rank * 32 + cu;
    const int slot2 = rank * 32 + cu2;

    // ---- Wih2/Whh2 row -> registers (64 u64 = 128 floats)
    u64 w2[64];
    {
        const int gr = (j1 >> 5) * 128 + rank * 32 + (j1 & 31);
        const float* src = (m2 ? Whh2 : Wih2) + (size_t)gr * 128;
        #pragma unroll
        for (int k = 0; k < 32; k++) {
            ulonglong2 v = ((const ulonglong2*)src)[k];
            w2[2 * k] = v.x; w2[2 * k + 1] = v.y;
        }
    }

    // ---- Whh1 slice -> SMEM
    for (int idx = tid; idx < 128 * 32; idx += 256) {
        int j = idx >> 5, k4 = idx & 31;
        int gr = (j >> 5) * 128 + rank * 32 + (j & 31);
        ((float4*)(sW1 + j * WSTRIDE))[k4] = ((const float4*)(Whh1 + (size_t)gr * 128))[k4];
    }
    if (tid < 128) {
        int gr = (tid >> 5) * 128 + rank * 32 + (tid & 31);
        bias1s[tid] = bih1[gr] + bhh1[gr];
        bias2s[tid] = bih2[gr] + bhh2[gr];
        wih1s[tid]  = Wih1[gr];
    }
    for (int idx = tid; idx < GB * TSEQ; idx += 256) {
        int b = idx >> 9, tt = idx & (TSEQ - 1);
        xs[b][tt] = x[(size_t)(bg0 + b) * TSEQ + tt];
    }
    for (int idx = tid; idx < 2 * GB * HDIM; idx += 256) {
        ((float*)h1bc)[idx] = 0.f;
        ((float*)c1bc)[idx] = 0.f;
        ((float*)h2bc)[idx] = 0.f;
    }
    const uint32_t mb1a = (uint32_t)__cvta_generic_to_shared(&mbar[0]);
    const uint32_t mb2a = (uint32_t)__cvta_generic_to_shared(&mbar[1]);
    if (tid == 0) { mbar_init(mb1a, 4); mbar_init(mb2a, 4); }
    __syncthreads();
    cluster_sync_();   // peers see zeroed buffers + initialized mbarriers

    float c1s[2] = {0.f, 0.f};
    float c2s[2] = {0.f, 0.f};

    for (int i = 0; i <= TSEQ; i++) {
        const int p  = i & 1;
        const int pn = p ^ 1;
        const uint32_t wpar = (uint32_t)pn;   // parity of phase i-1

        // ===== wait h1/c1(i-1), then mv1: row j1, batches 4bh..4bh+3 =====
        if (i > 0) mbar_wait(mb1a, wpar);
        if (i < TSEQ) {
            const ulonglong2* wp = (const ulonglong2*)(sW1 + j1 * WSTRIDE);
            const ulonglong2* hA = (const ulonglong2*)(h1bc[p][4 * bh + 0]);
            const ulonglong2* hB = (const ulonglong2*)(h1bc[p][4 * bh + 1]);
            const ulonglong2* hC = (const ulonglong2*)(h1bc[p][4 * bh + 2]);
            const ulonglong2* hD = (const ulonglong2*)(h1bc[p][4 * bh + 3]);
            u64 a0 = 0, a1 = 0, a2 = 0, a3 = 0;
            #pragma unroll
            for (int k = 0; k < 32; k++) {
                ulonglong2 w = wp[k];
                ulonglong2 v0 = hA[k], v1 = hB[k], v2 = hC[k], v3 = hD[k];
                a0 = ffma2(w.x, v0.x, a0); a0 = ffma2(w.y, v0.y, a0);
                a1 = ffma2(w.x, v1.x, a1); a1 = ffma2(w.y, v1.y, a1);
                a2 = ffma2(w.x, v2.x, a2); a2 = ffma2(w.y, v2.y, a2);
                a3 = ffma2(w.x, v3.x, a3); a3 = ffma2(w.y, v3.y, a3);
            }
            g1buf[j1 * GSTRIDE + 4 * bh + 0] = sum2(a0);
            g1buf[j1 * GSTRIDE + 4 * bh + 1] = sum2(a1);
            g1buf[j1 * GSTRIDE + 4 * bh + 2] = sum2(a2);
            g1buf[j1 * GSTRIDE + 4 * bh + 3] = sum2(a3);
        }

        // ===== wait h2(i-2), then mv2: reg row . (c1(i-1) | h2(i-2)), 8 batches
        if (i > 0) {
            mbar_wait(mb2a, wpar);
            const float* inb = m2 ? &h2bc[p][0][0] : &c1bc[p][0][0];
            const ulonglong2* i0 = (const ulonglong2*)(inb + 0 * HDIM);
            const ulonglong2* i1 = (const ulonglong2*)(inb + 1 * HDIM);
            const ulonglong2* i2 = (const ulonglong2*)(inb + 2 * HDIM);
            const ulonglong2* i3 = (const ulonglong2*)(inb + 3 * HDIM);
            const ulonglong2* i4 = (const ulonglong2*)(inb + 4 * HDIM);
            const ulonglong2* i5 = (const ulonglong2*)(inb + 5 * HDIM);
            const ulonglong2* i6 = (const ulonglong2*)(inb + 6 * HDIM);
            const ulonglong2* i7 = (const ulonglong2*)(inb + 7 * HDIM);
            u64 a0 = 0, a1 = 0, a2 = 0, a3 = 0, a4 = 0, a5 = 0, a6 = 0, a7 = 0;
            #pragma unroll
            for (int k = 0; k < 32; k++) {
                u64 wa = w2[2 * k], wb = w2[2 * k + 1];
                ulonglong2 v0 = i0[k], v1 = i1[k], v2 = i2[k], v3 = i3[k];
                a0 = ffma2(wa, v0.x, a0); a0 = ffma2(wb, v0.y, a0);
                a1 = ffma2(wa, v1.x, a1); a1 = ffma2(wb, v1.y, a1);
                a2 = ffma2(wa, v2.x, a2); a2 = ffma2(wb, v2.y, a2);
                a3 = ffma2(wa, v3.x, a3); a3 = ffma2(wb, v3.y, a3);
                ulonglong2 v4 = i4[k], v5 = i5[k], v6 = i6[k], v7 = i7[k];
                a4 = ffma2(wa, v4.x, a4); a4 = ffma2(wb, v4.y, a4);
                a5 = ffma2(wa, v5.x, a5); a5 = ffma2(wb, v5.y, a5);
                a6 = ffma2(wa, v6.x, a6); a6 = ffma2(wb, v6.y, a6);
                a7 = ffma2(wa, v7.x, a7); a7 = ffma2(wb, v7.y, a7);
            }
            float* pr = &part2[tid * GSTRIDE];
            pr[0] = sum2(a0); pr[1] = sum2(a1); pr[2] = sum2(a2); pr[3] = sum2(a3);
            pr[4] = sum2(a4); pr[5] = sum2(a5); pr[6] = sum2(a6); pr[7] = sum2(a7);
        }
        __syncthreads();   // all matvec reads/writes of iter i ordered before cells

        // ===== cell1 (tid<128): step i, batches cb and cb+4 =====
        if (tid < 128) {
            if (i < TSEQ) {
                #pragma unroll
                for (int q = 0; q < 2; q++) {
                    int b = cb + 4 * q;
                    float xv = xs[b][i];
                    float gi = g1buf[(cu)      * GSTRIDE + b] + fmaf(wih1s[cu],      xv, bias1s[cu]);
                    float gf = g1buf[(32 + cu) * GSTRIDE + b] + fmaf(wih1s[32 + cu], xv, bias1s[32 + cu]);
                    float gg = g1buf[(64 + cu) * GSTRIDE + b] + fmaf(wih1s[64 + cu], xv, bias1s[64 + cu]);
                    float go = g1buf[(96 + cu) * GSTRIDE + b] + fmaf(wih1s[96 + cu], xv, bias1s[96 + cu]);
                    c1s[q] = sigm(gf) * c1s[q] + sigm(gi) * tanh_fast(gg);
                    float h1n = sigm(go) * tanh_fast(c1s[q]);
                    #pragma unroll
                    for (int r = 0; r < 4; r++) {
                        st_cluster_f32(&h1bc[pn][b][slot1], r, h1n);
                        st_cluster_f32(&c1bc[pn][b][slot1], r, c1s[q]);
                    }
                }
                asm volatile("bar.sync 1, 128;" ::: "memory");
                if (tid == 0) {
                    #pragma unroll
                    for (int r = 0; r < 4; r++) mbar_arrive_rank(mb1a, r);
                }
            }
        } else {
            // ===== cell2 (tid>=128): step i-1, batches cb2 and cb2+4 =====
            if (i > 0) {
                #pragma unroll
                for (int q = 0; q < 2; q++) {
                    int b = cb2 + 4 * q;
                    float gi = part2[(cu2)      * GSTRIDE + b] + part2[(128 + cu2)      * GSTRIDE + b] + bias2s[cu2];
                    float gf = part2[(32 + cu2) * GSTRIDE + b] + part2[(128 + 32 + cu2) * GSTRIDE + b] + bias2s[32 + cu2];
                    float gg = part2[(64 + cu2) * GSTRIDE + b] + part2[(128 + 64 + cu2) * GSTRIDE + b] + bias2s[64 + cu2];
                    float go = part2[(96 + cu2) * GSTRIDE + b] + part2[(128 + 96 + cu2) * GSTRIDE + b] + bias2s[96 + cu2];
                    c2s[q] = sigm(gf) * c2s[q] + sigm(gi) * tanh_fast(gg);
                    float h2n = sigm(go) * tanh_fast(c2s[q]);
                    if (i < TSEQ) {
                        #pragma unroll
                        for (int r = 0; r < 4; r++)
                            st_cluster_f32(&h2bc[pn][b][slot2], r, h2n);
                    }
                    g_h2[(size_t)(i - 1) * (BATCH * HDIM)
                         + (size_t)(bg0 + b) * HDIM + slot2] = h2n;
                }
            }
            if (i < TSEQ) {
                asm volatile("bar.sync 2, 128;" ::: "memory");
                if (tid == 128) {
                    #pragma unroll
                    for (int r = 0; r < 4; r++) mbar_arrive_rank(mb2a, r);
                }
            }
        }
    }
}

// ---------------------------------------------------------------------------
__global__ void dots_kernel(const float* __restrict__ w_t)
{
    int gid  = blockIdx.x * blockDim.x + threadIdx.x;
    int gw   = gid >> 5;
    int lane = gid & 31;
    if (gw >= TSEQ * BATCH) return;
    float4 h = *(const float4*)(g_h2 + (size_t)gw * HDIM + lane * 4);
    float4 a = *(const float4*)(w_t + lane * 4);
    float4 o = *(const float4*)(w_t + HDIM + lane * 4);
    float dh   = h.x * a.x + h.y * a.y + h.z * a.z + h.w * a.w;
    float dold = h.x * o.x + h.y * o.y + h.z * o.z + h.w * o.w;
    #pragma unroll
    for (int off = 16; off; off >>= 1) {
        dh   += __shfl_down_sync(0xffffffffu, dh, off);
        dold += __shfl_down_sync(0xffffffffu, dold, off);
    }
    if (lane == 0) { g_dh[gw] = dh; g_dold[gw] = dold; }
}

// ---------------------------------------------------------------------------
__global__ void __launch_bounds__(256, 1)
attn_fc_kernel(const float* __restrict__ fcW, const float* __restrict__ fcb,
               float* __restrict__ out)
{
    extern __shared__ float sm[];
    float* sFcT = sm;                       // [128][132]
    float* sPre = sFcT + 128 * RSTRIDE;     // [128][132]
    float* sE   = sPre + 128 * RSTRIDE;     // [33][128]
    float* sHd  = sE + 33 * 128;            // [128]
    float* sFcb = sHd + 128;                // [128]
    float* sRed = sFcb + 128;               // [256]

    const int t    = blockIdx.x;
    const int tid  = threadIdx.x;
    const int lane = tid & 31;
    const int warp = tid >> 5;

    for (int idx = tid; idx < 128 * 128; idx += 256) {
        int c = idx >> 7, h = idx & 127;
        sFcT[h * RSTRIDE + c] = fcW[idx];
    }
    if (tid < 128) {
        sFcb[tid] = fcb[tid];
        sHd[tid]  = g_dh[t * BATCH + tid];
    }
    __syncthreads();

    const int s_min = (t < 32) ? (32 - t) : 0;
    const int nsc   = (33 - s_min) * 128;
    float lmax = -1e30f;
    for (int n = tid; n < nsc; n += 256) {
        int s = s_min + (n >> 7), b = n & 127;
        int idx = t - 33 + s;
        float sc = sHd[b] + (idx >= 0 ? g_dold[idx * BATCH + b] : 0.f);
        sE[s * 128 + b] = sc;
        lmax = fmaxf(lmax, sc);
    }
    sRed[tid] = lmax; __syncthreads();
    for (int off = 128; off; off >>= 1) {
        if (tid < off) sRed[tid] = fmaxf(sRed[tid], sRed[tid + off]);
        __syncthreads();
    }
    float mx = sRed[0];
    __syncthreads();
    float lsum = 0.f;
    for (int n = tid; n < nsc; n += 256) {
        int s = s_min + (n >> 7), b = n & 127;
        float e = __expf(sE[s * 128 + b] - mx);
        sE[s * 128 + b] = e;
        lsum += e;
    }
    sRed[tid] = lsum; __syncthreads();
    for (int off = 128; off; off >>= 1) {
        if (tid < off) sRed[tid] += sRed[tid + off];
        __syncthreads();
    }
    float inv = __fdividef(1.f, sRed[0]);
    __syncthreads();

    const int s_att = (t < 33) ? (33 - t) : 0;
    for (int b = warp; b < 128; b += 8) {
        float4 acc; acc.x = acc.y = acc.z = acc.w = 0.f;
        for (int s = s_att; s < 33; s++) {
            float w  = sE[s * 128 + b];
            float4 v = *(const float4*)(g_h2 + (size_t)(t - 33 + s) * (BATCH * HDIM)
                                              + (size_t)b * HDIM + lane * 4);
            acc.x += w * v.x; acc.y += w * v.y; acc.z += w * v.z; acc.w += w * v.w;
        }
        float4 hc = *(const float4*)(g_h2 + (size_t)t * (BATCH * HDIM)
                                           + (size_t)b * HDIM + lane * 4);
        float4 pre;
        pre.x = hc.x + inv * acc.x; pre.y = hc.y + inv * acc.y;
        pre.z = hc.z + inv * acc.z; pre.w = hc.w + inv * acc.w;
        *(float4*)(sPre + b * RSTRIDE + lane * 4) = pre;
    }
    __syncthreads();

    const int c0 = lane * 4;
    float4 bias = *(const float4*)(sFcb + c0);
    for (int r = 0; r < 4; r++) {
        int b0 = (warp + 8 * r) * 4;
        float4 a0, a1, a2, a3;
        a0.x=a0.y=a0.z=a0.w=0.f; a1=a0; a2=a0; a3=a0;
        const float4* p0 = (const float4*)(sPre + (size_t)(b0 + 0) * RSTRIDE);
        const float4* p1 = (const float4*)(sPre + (size_t)(b0 + 1) * RSTRIDE);
        const float4* p2 = (const float4*)(sPre + (size_t)(b0 + 2) * RSTRIDE);
        const float4* p3 = (const float4*)(sPre + (size_t)(b0 + 3) * RSTRIDE);
        #pragma unroll
        for (int h4 = 0; h4 < 32; h4++) {
            float4 q0 = p0[h4], q1 = p1[h4], q2 = p2[h4], q3 = p3[h4];
            #pragma unroll
            for (int hh = 0; hh < 4; hh++) {
                float4 w = *(const float4*)(sFcT + (h4 * 4 + hh) * RSTRIDE + c0);
                float v0 = (&q0.x)[hh], v1 = (&q1.x)[hh], v2 = (&q2.x)[hh], v3 = (&q3.x)[hh];
                a0.x += v0 * w.x; a0.y += v0 * w.y; a0.z += v0 * w.z; a0.w += v0 * w.w;
                a1.x += v1 * w.x; a1.y += v1 * w.y; a1.z += v1 * w.z; a1.w += v1 * w.w;
                a2.x += v2 * w.x; a2.y += v2 * w.y; a2.z += v2 * w.z; a2.w += v2 * w.w;
                a3.x += v3 * w.x; a3.y += v3 * w.y; a3.z += v3 * w.z; a3.w += v3 * w.w;
            }
        }
        a0.x += bias.x; a0.y += bias.y; a0.z += bias.z; a0.w += bias.w;
        a1.x += bias.x; a1.y += bias.y; a1.z += bias.z; a1.w += bias.w;
        a2.x += bias.x; a2.y += bias.y; a2.z += bias.z; a2.w += bias.w;
        a3.x += bias.x; a3.y += bias.y; a3.z += bias.z; a3.w += bias.w;
        size_t obase = (size_t)t * 128 + c0;
        *(float4*)(out + (size_t)(b0 + 0) * (TSEQ * 128) + obase) = a0;
        *(float4*)(out + (size_t)(b0 + 1) * (TSEQ * 128) + obase) = a1;
        *(float4*)(out + (size_t)(b0 + 2) * (TSEQ * 128) + obase) = a2;
        *(float4*)(out + (size_t)(b0 + 3) * (TSEQ * 128) + obase) = a3;
    }
}

// ---------------------------------------------------------------------------
extern "C" void kernel_launch(void* const* d_in, const int* in_sizes, int n_in,
                              void* d_out, int out_size)
{
    const float* x    = (const float*)d_in[0];
    const float* Wih1 = (const float*)d_in[1];
    const float* Whh1 = (const float*)d_in[2];
    const float* bih1 = (const float*)d_in[3];
    const float* bhh1 = (const float*)d_in[4];
    const float* Wih2 = (const float*)d_in[5];
    const float* Whh2 = (const float*)d_in[6];
    const float* bih2 = (const float*)d_in[7];
    const float* bhh2 = (const float*)d_in[8];
    const float* w_t  = (const float*)d_in[9];
    const float* fcW  = (const float*)d_in[10];
    const float* fcb  = (const float*)d_in[11];
    float* out = (float*)d_out;

    const int smem1 = 128 * WSTRIDE * (int)sizeof(float);   // 67584
    const int smem3 = (2 * 128 * RSTRIDE + 33 * 128 + 128 + 128 + 256) * (int)sizeof(float);

    cudaFuncSetAttribute(lstm_seq_kernel, cudaFuncAttributeMaxDynamicSharedMemorySize, smem1);
    cudaFuncSetAttribute(attn_fc_kernel,  cudaFuncAttributeMaxDynamicSharedMemorySize, smem3);

    lstm_seq_kernel<<<64, 256, smem1>>>(x, Wih1, Whh1, bih1, bhh1,
                                        Wih2, Whh2, bih2, bhh2);
    dots_kernel<<<(TSEQ * BATCH * 32) / 256, 256>>>(w_t);
    attn_fc_kernel<<<TSEQ, 256, smem3>>>(fcW, fcb, out);
}

// round 11
// speedup vs baseline: 1.6185x; 1.6185x over previous
#include <cuda_runtime.h>
#include <cstdint>

#define HDIM 128
#define TSEQ 512
#define BATCH 128
#define GB 4
#define RSTRIDE 132
#define WSTRIDE 132
#define ASTRIDE 132     // activation row stride; dims 64..127 live at offset 68 (bank-shift gap)
#define GSTRIDE 9       // gate-buffer row stride -> conflict-free scalar access

typedef unsigned long long u64;

__device__ float g_h2[(size_t)TSEQ * BATCH * HDIM];   // [t][b][h]
__device__ float g_dold[TSEQ * BATCH];
__device__ float g_dh[TSEQ * BATCH];

__device__ __forceinline__ float sigm(float x) {
    return __fdividef(1.f, 1.f + __expf(-x));
}
__device__ __forceinline__ float tanh_fast(float x) {
    x = fminf(fmaxf(x, -15.f), 15.f);
    float e = __expf(2.f * x);
    return __fdividef(e - 1.f, e + 1.f);
}
__device__ __forceinline__ u64 ffma2(u64 a, u64 b, u64 c) {
    u64 d;
    asm("fma.rn.f32x2 %0, %1, %2, %3;" : "=l"(d) : "l"(a), "l"(b), "l"(c));
    return d;
}
__device__ __forceinline__ float sum2(u64 v) {
    float lo, hi;
    asm("mov.b64 {%0, %1}, %2;" : "=f"(lo), "=f"(hi) : "l"(v));
    return lo + hi;
}
__device__ __forceinline__ void st_cluster_f32(float* p, int rank, float v) {
    uint32_t la = (uint32_t)__cvta_generic_to_shared(p);
    uint32_t ra;
    asm volatile("mapa.shared::cluster.u32 %0, %1, %2;" : "=r"(ra) : "r"(la), "r"(rank));
    asm volatile("st.shared::cluster.f32 [%0], %1;" :: "r"(ra), "f"(v) : "memory");
}
__device__ __forceinline__ void mbar_init(uint32_t a, uint32_t cnt) {
    asm volatile("mbarrier.init.shared.b64 [%0], %1;" :: "r"(a), "r"(cnt) : "memory");
}
__device__ __forceinline__ void mbar_arrive_rank(uint32_t local_addr, uint32_t rank) {
    asm volatile(
        "{\n\t.reg .b32 ra;\n\t"
        "mapa.shared::cluster.u32 ra, %0, %1;\n\t"
        "mbarrier.arrive.release.cluster.shared::cluster.b64 _, [ra];\n\t}"
        :: "r"(local_addr), "r"(rank) : "memory");
}
__device__ __forceinline__ void mbar_wait(uint32_t addr, uint32_t parity) {
    asm volatile(
        "{\n\t.reg .pred P;\n"
        "WL_%=:\n\t"
        "mbarrier.try_wait.parity.acquire.cluster.shared::cta.b64 P, [%0], %1, 0x989680;\n\t"
        "@P bra WD_%=;\n\t"
        "bra WL_%=;\n"
        "WD_%=:\n\t}"
        :: "r"(addr), "r"(parity) : "memory");
}
__device__ __forceinline__ void cluster_sync_() {
    asm volatile("barrier.cluster.arrive.aligned;" ::: "memory");
    asm volatile("barrier.cluster.wait.aligned;" ::: "memory");
}

// ---------------------------------------------------------------------------
// Phase 1: 32 clusters x 4 CTAs, 4 batches/cluster, 256 threads/CTA.
// R5 structure (split mbarriers, pipelined cell1/cell2 on disjoint warp
// halves, no cluster fence) with crossbar-optimized tiling:
//   mv1: thread = (row j1, k-half kh at lane bit 4). Acts use a GAP layout
//        (dims 64.. at float-offset 68) so the two kh base addresses fall in
//        different banks -> conflict-free. shfl_xor(16) combines halves.
//   mv2: thread = (row-PAIR q -> gate rows 2q,2q+1 of [Wih2;Whh2], k-half
//        kh). Weights: 2x64 floats in 64 u64 REGISTERS. Act loads per
//        thread: 64 (was 128). shfl_xor(16) combines halves; kh==0 writes
//        part2 rows 2q,2q+1 (stride 9 -> conflict-free scalar I/O).
// ---------------------------------------------------------------------------
__global__ void __launch_bounds__(256, 1) __cluster_dims__(4, 1, 1)
lstm_seq_kernel(const float* __restrict__ x,
                const float* __restrict__ Wih1, const float* __restrict__ Whh1,
                const float* __restrict__ bih1, const float* __restrict__ bhh1,
                const float* __restrict__ Wih2, const float* __restrict__ Whh2,
                const float* __restrict__ bih2, const float* __restrict__ bhh2)
{
    extern __shared__ float sW1[];                     // [128][WSTRIDE]

    __shared__ __align__(16) float h1bc[2][GB * ASTRIDE];  // gap layout per batch row
    __shared__ __align__(16) float c1bc[2][GB * ASTRIDE];
    __shared__ __align__(16) float h2bc[2][GB * ASTRIDE];
    __shared__ float xs[GB][TSEQ];
    __shared__ float g1buf[128 * GSTRIDE];             // [row*9 + b]
    __shared__ float part2[256 * GSTRIDE];             // [vrow*9 + b]
    __shared__ float bias1s[128], bias2s[128], wih1s[128];
    __shared__ __align__(8) u64 mbar[2];

    const int tid  = threadIdx.x;
    const int rank = blockIdx.x & 3;
    const int bg0  = (blockIdx.x >> 2) * GB;

    // matvec roles: q/j1 in 0..127 paired across kh (lane bit 4)
    const int q  = (tid & 15) | ((tid >> 5) << 4);   // 0..127
    const int kh = (tid >> 4) & 1;
    const int j1 = q;                                // mv1 row
    const int r0 = 2 * q, r1 = 2 * q + 1;            // mv2 combined rows (0..255)
    const int mm = q >> 6;                           // 0 = Wih2 rows, 1 = Whh2 rows
    // cell roles
    const int cu  = tid & 31,          cb  = tid >> 5;           // cell1 (tid<128)
    const int cu2 = (tid - 128) & 31,  cb2 = (tid - 128) >> 5;   // cell2 (tid>=128)
    const int slot1 = rank * 32 + cu;
    const int slot2 = rank * 32 + cu2;
    const int pos1  = slot1 + (slot1 >= 64 ? 4 : 0); // gap-layout position
    const int pos2  = slot2 + (slot2 >= 64 ? 4 : 0);

    // ---- mv2 weights -> registers: rows r0, r1, k-half kh (2 x 32 u64)
    u64 wA[32], wB[32];
    {
        const float* M = mm ? Whh2 : Wih2;
        const int lr0 = r0 & 127, lr1 = r1 & 127;
        const int gr0 = (lr0 >> 5) * 128 + rank * 32 + (lr0 & 31);
        const int gr1 = (lr1 >> 5) * 128 + rank * 32 + (lr1 & 31);
        const float* s0 = M + (size_t)gr0 * 128 + kh * 64;
        const float* s1 = M + (size_t)gr1 * 128 + kh * 64;
        #pragma unroll
        for (int k = 0; k < 16; k++) {
            ulonglong2 v0 = ((const ulonglong2*)s0)[k];
            ulonglong2 v1 = ((const ulonglong2*)s1)[k];
            wA[2 * k] = v0.x; wA[2 * k + 1] = v0.y;
            wB[2 * k] = v1.x; wB[2 * k + 1] = v1.y;
        }
    }

    // ---- Whh1 slice -> SMEM (full rows, no gap)
    for (int idx = tid; idx < 128 * 32; idx += 256) {
        int j = idx >> 5, k4 = idx & 31;
        int gr = (j >> 5) * 128 + rank * 32 + (j & 31);
        ((float4*)(sW1 + j * WSTRIDE))[k4] = ((const float4*)(Whh1 + (size_t)gr * 128))[k4];
    }
    if (tid < 128) {
        int gr = (tid >> 5) * 128 + rank * 32 + (tid & 31);
        bias1s[tid] = bih1[gr] + bhh1[gr];
        bias2s[tid] = bih2[gr] + bhh2[gr];
        wih1s[tid]  = Wih1[gr];
    }
    for (int idx = tid; idx < GB * TSEQ; idx += 256) {
        int b = idx >> 9, tt = idx & (TSEQ - 1);
        xs[b][tt] = x[(size_t)(bg0 + b) * TSEQ + tt];
    }
    for (int idx = tid; idx < 2 * GB * ASTRIDE; idx += 256) {
        ((float*)h1bc)[idx] = 0.f;
        ((float*)c1bc)[idx] = 0.f;
        ((float*)h2bc)[idx] = 0.f;
    }
    const uint32_t mb1a = (uint32_t)__cvta_generic_to_shared(&mbar[0]);
    const uint32_t mb2a = (uint32_t)__cvta_generic_to_shared(&mbar[1]);
    if (tid == 0) { mbar_init(mb1a, 4); mbar_init(mb2a, 4); }
    __syncthreads();
    cluster_sync_();   // peers see zeroed buffers + initialized mbarriers

    float c1s = 0.f, c2s = 0.f;

    for (int i = 0; i <= TSEQ; i++) {
        const int p  = i & 1;
        const int pn = p ^ 1;
        const uint32_t wpar = (uint32_t)pn;   // parity of phase i-1

        // ===== wait h1/c1(i-1), then mv1: row j1, k-half kh, 4 batches =====
        if (i > 0) mbar_wait(mb1a, wpar);
        if (i < TSEQ) {
            const ulonglong2* wp = (const ulonglong2*)(sW1 + j1 * WSTRIDE + kh * 64);
            const ulonglong2* hA = (const ulonglong2*)(&h1bc[p][0 * ASTRIDE + kh * 68]);
            const ulonglong2* hB = (const ulonglong2*)(&h1bc[p][1 * ASTRIDE + kh * 68]);
            const ulonglong2* hC = (const ulonglong2*)(&h1bc[p][2 * ASTRIDE + kh * 68]);
            const ulonglong2* hD = (const ulonglong2*)(&h1bc[p][3 * ASTRIDE + kh * 68]);
            u64 a0 = 0, a1 = 0, a2 = 0, a3 = 0;
            #pragma unroll
            for (int k = 0; k < 16; k++) {
                ulonglong2 w = wp[k];
                ulonglong2 v0 = hA[k], v1 = hB[k], v2 = hC[k], v3 = hD[k];
                a0 = ffma2(w.x, v0.x, a0); a0 = ffma2(w.y, v0.y, a0);
                a1 = ffma2(w.x, v1.x, a1); a1 = ffma2(w.y, v1.y, a1);
                a2 = ffma2(w.x, v2.x, a2); a2 = ffma2(w.y, v2.y, a2);
                a3 = ffma2(w.x, v3.x, a3); a3 = ffma2(w.y, v3.y, a3);
            }
            float s0 = sum2(a0), s1 = sum2(a1), s2 = sum2(a2), s3 = sum2(a3);
            s0 += __shfl_xor_sync(0xffffffffu, s0, 16);
            s1 += __shfl_xor_sync(0xffffffffu, s1, 16);
            s2 += __shfl_xor_sync(0xffffffffu, s2, 16);
            s3 += __shfl_xor_sync(0xffffffffu, s3, 16);
            if (kh == 0) {
                g1buf[j1 * GSTRIDE + 0] = s0;
                g1buf[j1 * GSTRIDE + 1] = s1;
                g1buf[j1 * GSTRIDE + 2] = s2;
                g1buf[j1 * GSTRIDE + 3] = s3;
            }
        }

        // ===== wait h2(i-2), then mv2: rows r0,r1, k-half kh, 4 batches =====
        if (i > 0) {
            mbar_wait(mb2a, wpar);
            const float* inb = mm ? &h2bc[p][0] : &c1bc[p][0];
            const ulonglong2* i0 = (const ulonglong2*)(inb + 0 * ASTRIDE + kh * 68);
            const ulonglong2* i1 = (const ulonglong2*)(inb + 1 * ASTRIDE + kh * 68);
            const ulonglong2* i2 = (const ulonglong2*)(inb + 2 * ASTRIDE + kh * 68);
            const ulonglong2* i3 = (const ulonglong2*)(inb + 3 * ASTRIDE + kh * 68);
            u64 a00 = 0, a01 = 0, a02 = 0, a03 = 0;
            u64 a10 = 0, a11 = 0, a12 = 0, a13 = 0;
            #pragma unroll
            for (int k = 0; k < 16; k++) {
                ulonglong2 v0 = i0[k], v1 = i1[k], v2 = i2[k], v3 = i3[k];
                u64 wa0 = wA[2 * k], wa1 = wA[2 * k + 1];
                a00 = ffma2(wa0, v0.x, a00); a00 = ffma2(wa1, v0.y, a00);
                a01 = ffma2(wa0, v1.x, a01); a01 = ffma2(wa1, v1.y, a01);
                a02 = ffma2(wa0, v2.x, a02); a02 = ffma2(wa1, v2.y, a02);
                a03 = ffma2(wa0, v3.x, a03); a03 = ffma2(wa1, v3.y, a03);
                u64 wb0 = wB[2 * k], wb1 = wB[2 * k + 1];
                a10 = ffma2(wb0, v0.x, a10); a10 = ffma2(wb1, v0.y, a10);
                a11 = ffma2(wb0, v1.x, a11); a11 = ffma2(wb1, v1.y, a11);
                a12 = ffma2(wb0, v2.x, a12); a12 = ffma2(wb1, v2.y, a12);
                a13 = ffma2(wb0, v3.x, a13); a13 = ffma2(wb1, v3.y, a13);
            }
            float s00 = sum2(a00), s01 = sum2(a01), s02 = sum2(a02), s03 = sum2(a03);
            float s10 = sum2(a10), s11 = sum2(a11), s12 = sum2(a12), s13 = sum2(a13);
            s00 += __shfl_xor_sync(0xffffffffu, s00, 16);
            s01 += __shfl_xor_sync(0xffffffffu, s01, 16);
            s02 += __shfl_xor_sync(0xffffffffu, s02, 16);
            s03 += __shfl_xor_sync(0xffffffffu, s03, 16);
            s10 += __shfl_xor_sync(0xffffffffu, s10, 16);
            s11 += __shfl_xor_sync(0xffffffffu, s11, 16);
            s12 += __shfl_xor_sync(0xffffffffu, s12, 16);
            s13 += __shfl_xor_sync(0xffffffffu, s13, 16);
            if (kh == 0) {
                float* p0 = &part2[r0 * GSTRIDE];
                float* p1 = &part2[r1 * GSTRIDE];
                p0[0] = s00; p0[1] = s01; p0[2] = s02; p0[3] = s03;
                p1[0] = s10; p1[1] = s11; p1[2] = s12; p1[3] = s13;
            }
        }
        __syncthreads();   // gate buffers complete; prior-iter readers done

        // ===== cell1 (tid<128): step i =====
        if (tid < 128) {
            if (i < TSEQ) {
                float xv = xs[cb][i];
                float gi = g1buf[(cu)      * GSTRIDE + cb] + fmaf(wih1s[cu],      xv, bias1s[cu]);
                float gf = g1buf[(32 + cu) * GSTRIDE + cb] + fmaf(wih1s[32 + cu], xv, bias1s[32 + cu]);
                float gg = g1buf[(64 + cu) * GSTRIDE + cb] + fmaf(wih1s[64 + cu], xv, bias1s[64 + cu]);
                float go = g1buf[(96 + cu) * GSTRIDE + cb] + fmaf(wih1s[96 + cu], xv, bias1s[96 + cu]);
                c1s = sigm(gf) * c1s + sigm(gi) * tanh_fast(gg);
                float h1n = sigm(go) * tanh_fast(c1s);
                #pragma unroll
                for (int r = 0; r < 4; r++) {
                    st_cluster_f32(&h1bc[pn][cb * ASTRIDE + pos1], r, h1n);
                    st_cluster_f32(&c1bc[pn][cb * ASTRIDE + pos1], r, c1s);
                }
                asm volatile("bar.sync 1, 128;" ::: "memory");
                if (tid == 0) {
                    #pragma unroll
                    for (int r = 0; r < 4; r++) mbar_arrive_rank(mb1a, r);
                }
            }
        } else {
            // ===== cell2 (tid>=128): step i-1 =====
            if (i > 0) {
                float gi = part2[(cu2)      * GSTRIDE + cb2] + part2[(128 + cu2)      * GSTRIDE + cb2] + bias2s[cu2];
                float gf = part2[(32 + cu2) * GSTRIDE + cb2] + part2[(128 + 32 + cu2) * GSTRIDE + cb2] + bias2s[32 + cu2];
                float gg = part2[(64 + cu2) * GSTRIDE + cb2] + part2[(128 + 64 + cu2) * GSTRIDE + cb2] + bias2s[64 + cu2];
                float go = part2[(96 + cu2) * GSTRIDE + cb2] + part2[(128 + 96 + cu2) * GSTRIDE + cb2] + bias2s[96 + cu2];
                c2s = sigm(gf) * c2s + sigm(gi) * tanh_fast(gg);
                float h2n = sigm(go) * tanh_fast(c2s);
                if (i < TSEQ) {
                    #pragma unroll
                    for (int r = 0; r < 4; r++)
                        st_cluster_f32(&h2bc[pn][cb2 * ASTRIDE + pos2], r, h2n);
                }
                g_h2[(size_t)(i - 1) * (BATCH * HDIM)
                     + (size_t)(bg0 + cb2) * HDIM + slot2] = h2n;
            }
            if (i < TSEQ) {
                asm volatile("bar.sync 2, 128;" ::: "memory");
                if (tid == 128) {
                    #pragma unroll
                    for (int r = 0; r < 4; r++) mbar_arrive_rank(mb2a, r);
                }
            }
        }
    }
}

// ---------------------------------------------------------------------------
__global__ void dots_kernel(const float* __restrict__ w_t)
{
    int gid  = blockIdx.x * blockDim.x + threadIdx.x;
    int gw   = gid >> 5;
    int lane = gid & 31;
    if (gw >= TSEQ * BATCH) return;
    float4 h = *(const float4*)(g_h2 + (size_t)gw * HDIM + lane * 4);
    float4 a = *(const float4*)(w_t + lane * 4);
    float4 o = *(const float4*)(w_t + HDIM + lane * 4);
    float dh   = h.x * a.x + h.y * a.y + h.z * a.z + h.w * a.w;
    float dold = h.x * o.x + h.y * o.y + h.z * o.z + h.w * o.w;
    #pragma unroll
    for (int off = 16; off; off >>= 1) {
        dh   += __shfl_down_sync(0xffffffffu, dh, off);
        dold += __shfl_down_sync(0xffffffffu, dold, off);
    }
    if (lane == 0) { g_dh[gw] = dh; g_dold[gw] = dold; }
}

// ---------------------------------------------------------------------------
__global__ void __launch_bounds__(256, 1)
attn_fc_kernel(const float* __restrict__ fcW, const float* __restrict__ fcb,
               float* __restrict__ out)
{
    extern __shared__ float sm[];
    float* sFcT = sm;                       // [128][132]
    float* sPre = sFcT + 128 * RSTRIDE;     // [128][132]
    float* sE   = sPre + 128 * RSTRIDE;     // [33][128]
    float* sHd  = sE + 33 * 128;            // [128]
    float* sFcb = sHd + 128;                // [128]
    float* sRed = sFcb + 128;               // [256]

    const int t    = blockIdx.x;
    const int tid  = threadIdx.x;
    const int lane = tid & 31;
    const int warp = tid >> 5;

    for (int idx = tid; idx < 128 * 128; idx += 256) {
        int c = idx >> 7, h = idx & 127;
        sFcT[h * RSTRIDE + c] = fcW[idx];
    }
    if (tid < 128) {
        sFcb[tid] = fcb[tid];
        sHd[tid]  = g_dh[t * BATCH + tid];
    }
    __syncthreads();

    const int s_min = (t < 32) ? (32 - t) : 0;
    const int nsc   = (33 - s_min) * 128;
    float lmax = -1e30f;
    for (int n = tid; n < nsc; n += 256) {
        int s = s_min + (n >> 7), b = n & 127;
        int idx = t - 33 + s;
        float sc = sHd[b] + (idx >= 0 ? g_dold[idx * BATCH + b] : 0.f);
        sE[s * 128 + b] = sc;
        lmax = fmaxf(lmax, sc);
    }
    sRed[tid] = lmax; __syncthreads();
    for (int off = 128; off; off >>= 1) {
        if (tid < off) sRed[tid] = fmaxf(sRed[tid], sRed[tid + off]);
        __syncthreads();
    }
    float mx = sRed[0];
    __syncthreads();
    float lsum = 0.f;
    for (int n = tid; n < nsc; n += 256) {
        int s = s_min + (n >> 7), b = n & 127;
        float e = __expf(sE[s * 128 + b] - mx);
        sE[s * 128 + b] = e;
        lsum += e;
    }
    sRed[tid] = lsum; __syncthreads();
    for (int off = 128; off; off >>= 1) {
        if (tid < off) sRed[tid] += sRed[tid + off];
        __syncthreads();
    }
    float inv = __fdividef(1.f, sRed[0]);
    __syncthreads();

    const int s_att = (t < 33) ? (33 - t) : 0;
    for (int b = warp; b < 128; b += 8) {
        float4 acc; acc.x = acc.y = acc.z = acc.w = 0.f;
        for (int s = s_att; s < 33; s++) {
            float w  = sE[s * 128 + b];
            float4 v = *(const float4*)(g_h2 + (size_t)(t - 33 + s) * (BATCH * HDIM)
                                              + (size_t)b * HDIM + lane * 4);
            acc.x += w * v.x; acc.y += w * v.y; acc.z += w * v.z; acc.w += w * v.w;
        }
        float4 hc = *(const float4*)(g_h2 + (size_t)t * (BATCH * HDIM)
                                           + (size_t)b * HDIM + lane * 4);
        float4 pre;
        pre.x = hc.x + inv * acc.x; pre.y = hc.y + inv * acc.y;
        pre.z = hc.z + inv * acc.z; pre.w = hc.w + inv * acc.w;
        *(float4*)(sPre + b * RSTRIDE + lane * 4) = pre;
    }
    __syncthreads();

    const int c0 = lane * 4;
    float4 bias = *(const float4*)(sFcb + c0);
    for (int r = 0; r < 4; r++) {
        int b0 = (warp + 8 * r) * 4;
        float4 a0, a1, a2, a3;
        a0.x=a0.y=a0.z=a0.w=0.f; a1=a0; a2=a0; a3=a0;
        const float4* p0 = (const float4*)(sPre + (size_t)(b0 + 0) * RSTRIDE);
        const float4* p1 = (const float4*)(sPre + (size_t)(b0 + 1) * RSTRIDE);
        const float4* p2 = (const float4*)(sPre + (size_t)(b0 + 2) * RSTRIDE);
        const float4* p3 = (const float4*)(sPre + (size_t)(b0 + 3) * RSTRIDE);
        #pragma unroll
        for (int h4 = 0; h4 < 32; h4++) {
            float4 q0 = p0[h4], q1 = p1[h4], q2 = p2[h4], q3 = p3[h4];
            #pragma unroll
            for (int hh = 0; hh < 4; hh++) {
                float4 w = *(const float4*)(sFcT + (h4 * 4 + hh) * RSTRIDE + c0);
                float v0 = (&q0.x)[hh], v1 = (&q1.x)[hh], v2 = (&q2.x)[hh], v3 = (&q3.x)[hh];
                a0.x += v0 * w.x; a0.y += v0 * w.y; a0.z += v0 * w.z; a0.w += v0 * w.w;
                a1.x += v1 * w.x; a1.y += v1 * w.y; a1.z += v1 * w.z; a1.w += v1 * w.w;
                a2.x += v2 * w.x; a2.y += v2 * w.y; a2.z += v2 * w.z; a2.w += v2 * w.w;
                a3.x += v3 * w.x; a3.y += v3 * w.y; a3.z += v3 * w.z; a3.w += v3 * w.w;
            }
        }
        a0.x += bias.x; a0.y += bias.y; a0.z += bias.z; a0.w += bias.w;
        a1.x += bias.x; a1.y += bias.y; a1.z += bias.z; a1.w += bias.w;
        a2.x += bias.x; a2.y += bias.y; a2.z += bias.z; a2.w += bias.w;
        a3.x += bias.x; a3.y += bias.y; a3.z += bias.z; a3.w += bias.w;
        size_t obase = (size_t)t * 128 + c0;
        *(float4*)(out + (size_t)(b0 + 0) * (TSEQ * 128) + obase) = a0;
        *(float4*)(out + (size_t)(b0 + 1) * (TSEQ * 128) + obase) = a1;
        *(float4*)(out + (size_t)(b0 + 2) * (TSEQ * 128) + obase) = a2;
        *(float4*)(out + (size_t)(b0 + 3) * (TSEQ * 128) + obase) = a3;
    }
}

// ---------------------------------------------------------------------------
extern "C" void kernel_launch(void* const* d_in, const int* in_sizes, int n_in,
                              void* d_out, int out_size)
{
    const float* x    = (const float*)d_in[0];
    const float* Wih1 = (const float*)d_in[1];
    const float* Whh1 = (const float*)d_in[2];
    const float* bih1 = (const float*)d_in[3];
    const float* bhh1 = (const float*)d_in[4];
    const float* Wih2 = (const float*)d_in[5];
    const float* Whh2 = (const float*)d_in[6];
    const float* bih2 = (const float*)d_in[7];
    const float* bhh2 = (const float*)d_in[8];
    const float* w_t  = (const float*)d_in[9];
    const float* fcW  = (const float*)d_in[10];
    const float* fcb  = (const float*)d_in[11];
    float* out = (float*)d_out;

    const int smem1 = 128 * WSTRIDE * (int)sizeof(float);   // 67584
    const int smem3 = (2 * 128 * RSTRIDE + 33 * 128 + 128 + 128 + 256) * (int)sizeof(float);

    cudaFuncSetAttribute(lstm_seq_kernel, cudaFuncAttributeMaxDynamicSharedMemorySize, smem1);
    cudaFuncSetAttribute(attn_fc_kernel,  cudaFuncAttributeMaxDynamicSharedMemorySize, smem3);

    lstm_seq_kernel<<<128, 256, smem1>>>(x, Wih1, Whh1, bih1, bhh1,
                                         Wih2, Whh2, bih2, bhh2);
    dots_kernel<<<(TSEQ * BATCH * 32) / 256, 256>>>(w_t);
    attn_fc_kernel<<<TSEQ, 256, smem3>>>(fcW, fcb, out);
}